// round 5
// baseline (speedup 1.0000x reference)
#include <cuda_runtime.h>
#include <cuda_bf16.h>

// Problem constants (fixed by the reference).
#define N_  512
#define L_  5
#define H_  8
#define D_  16
#define E_  10000

// Scratch: projected edge table P[e][l][h] = dot(edge_features[e], W[1+l][h]).
// E*L*H = 400,000 floats = 1.6 MB. Row stride per e = 40 floats = 160 B
// (16B-aligned, so float4 loads of [l][h0..3] / [l][h4..7] are legal).
__device__ float g_P[E_ * L_ * H_];

// ---------------------------------------------------------------------------
// Kernel 1: project every edge feature row through all (l, h) weight vectors.
// One thread per edge e. W (rows 1..L only) staged in shared memory; uniform
// warp access -> LDS broadcast, conflict-free.
// ---------------------------------------------------------------------------
__global__ void __launch_bounds__(128)
project_kernel(const float* __restrict__ F,   // [E, D]
               const float* __restrict__ W)   // [L+1, H*D]
{
    __shared__ float sW[L_ * H_ * D_];        // 640 floats, rows 1..L
    for (int i = threadIdx.x; i < L_ * H_ * D_; i += blockDim.x)
        sW[i] = W[H_ * D_ + i];               // skip row 0
    __syncthreads();

    int e = blockIdx.x * blockDim.x + threadIdx.x;
    if (e >= E_) return;

    // Load the 16-float feature row with 4x float4.
    const float4* fp = reinterpret_cast<const float4*>(F + (size_t)e * D_);
    float4 f0 = fp[0], f1 = fp[1], f2 = fp[2], f3 = fp[3];
    float fr[D_] = { f0.x, f0.y, f0.z, f0.w,
                     f1.x, f1.y, f1.z, f1.w,
                     f2.x, f2.y, f2.z, f2.w,
                     f3.x, f3.y, f3.z, f3.w };

    float out[L_ * H_];
    #pragma unroll
    for (int l = 0; l < L_; ++l) {
        #pragma unroll
        for (int h = 0; h < H_; ++h) {
            float acc = 0.0f;
            const float* w = &sW[(l * H_ + h) * D_];
            #pragma unroll
            for (int d = 0; d < D_; ++d)
                acc = fmaf(fr[d], w[d], acc);
            out[l * H_ + h] = acc;
        }
    }

    // 40 floats = 10 float4 stores, 16B-aligned (e*160 bytes).
    float4* dst = reinterpret_cast<float4*>(g_P + (size_t)e * (L_ * H_));
    #pragma unroll
    for (int i = 0; i < (L_ * H_) / 4; ++i) {
        float4 v = { out[4*i], out[4*i+1], out[4*i+2], out[4*i+3] };
        dst[i] = v;
    }
}

// ---------------------------------------------------------------------------
// Kernel 2: per (i, j) pair, gather P rows for the valid path edges, average,
// and scatter the 8 head values to out[h][i][j]. One thread per pair.
//
// IMPORTANT: indices arrive as int32 (the harness materializes the
// reference's int64 tensor as int32 — only float32/int32/bf16 exist in its
// dtype map). Index -1 => skip (== clip-to-0 + mask in the reference).
// Divisor = max(valid_count, 1). Any out-of-range value is treated as
// invalid (defensive: wrong-answer beats illegal-access for diagnosis).
// ---------------------------------------------------------------------------
__global__ void __launch_bounds__(256)
gather_kernel(const int* __restrict__ spe,   // [N, N, L] int32
              float* __restrict__ out)       // [H, N, N]
{
    int p = blockIdx.x * blockDim.x + threadIdx.x; // pair = i*N + j
    if (p >= N_ * N_) return;

    const int* sp = spe + (size_t)p * L_;

    float acc0 = 0.f, acc1 = 0.f, acc2 = 0.f, acc3 = 0.f;
    float acc4 = 0.f, acc5 = 0.f, acc6 = 0.f, acc7 = 0.f;
    int cnt = 0;

    #pragma unroll
    for (int l = 0; l < L_; ++l) {
        int e = __ldg(&sp[l]);
        if ((unsigned)e < (unsigned)E_) {   // e in [0, E): valid
            ++cnt;
            // P row chunk: byte offset e*160 + l*32, 16B-aligned.
            const float4* src =
                reinterpret_cast<const float4*>(g_P + (size_t)e * (L_ * H_) + l * H_);
            float4 a = src[0];
            float4 b = src[1];
            acc0 += a.x; acc1 += a.y; acc2 += a.z; acc3 += a.w;
            acc4 += b.x; acc5 += b.y; acc6 += b.z; acc7 += b.w;
        }
    }

    float inv = 1.0f / (float)(cnt > 0 ? cnt : 1);

    const int NN = N_ * N_;
    out[0 * NN + p] = acc0 * inv;
    out[1 * NN + p] = acc1 * inv;
    out[2 * NN + p] = acc2 * inv;
    out[3 * NN + p] = acc3 * inv;
    out[4 * NN + p] = acc4 * inv;
    out[5 * NN + p] = acc5 * inv;
    out[6 * NN + p] = acc6 * inv;
    out[7 * NN + p] = acc7 * inv;
}

// ---------------------------------------------------------------------------
// Launch: inputs in metadata order:
//   d_in[0] = edge_features_s      float32 [E*D]
//   d_in[1] = edge_weights         float32 [(L+1)*H*D]
//   d_in[2] = shortest_path_edges  int32   [N*N*L]   (int64 in ref -> int32)
// d_out = float32 [H*N*N]
// ---------------------------------------------------------------------------
extern "C" void kernel_launch(void* const* d_in, const int* in_sizes, int n_in,
                              void* d_out, int out_size)
{
    const float* F   = (const float*)d_in[0];
    const float* W   = (const float*)d_in[1];
    const int*   spe = (const int*)d_in[2];
    float*       out = (float*)d_out;

    project_kernel<<<(E_ + 127) / 128, 128>>>(F, W);
    gather_kernel<<<(N_ * N_ + 255) / 256, 256>>>(spe, out);
}

// round 6
// speedup vs baseline: 1.0035x; 1.0035x over previous
#include <cuda_runtime.h>
#include <cuda_bf16.h>

// Problem constants (fixed by the reference).
#define N_  512
#define L_  5
#define H_  8
#define D_  16
#define E_  10000

// Scratch: projected edge table P[e][l][h] = dot(edge_features[e], W[1+l][h]).
// E*L*H = 400,000 floats = 1.6 MB. Row stride per e = 40 floats = 160 B
// (16B-aligned, so float4 loads of [l][h0..3] / [l][h4..7] are legal).
__device__ float g_P[E_ * L_ * H_];

// ---------------------------------------------------------------------------
// Kernel 1: project every edge feature row through all (l, h) weight vectors.
// One thread per edge e. W (rows 1..L only) staged in shared memory; uniform
// warp access -> LDS broadcast, conflict-free.
// ---------------------------------------------------------------------------
__global__ void __launch_bounds__(128)
project_kernel(const float* __restrict__ F,   // [E, D]
               const float* __restrict__ W)   // [L+1, H*D]
{
    __shared__ float sW[L_ * H_ * D_];        // 640 floats, rows 1..L
    for (int i = threadIdx.x; i < L_ * H_ * D_; i += blockDim.x)
        sW[i] = W[H_ * D_ + i];               // skip row 0
    __syncthreads();

    int e = blockIdx.x * blockDim.x + threadIdx.x;
    if (e >= E_) return;

    // Load the 16-float feature row with 4x float4.
    const float4* fp = reinterpret_cast<const float4*>(F + (size_t)e * D_);
    float4 f0 = fp[0], f1 = fp[1], f2 = fp[2], f3 = fp[3];
    float fr[D_] = { f0.x, f0.y, f0.z, f0.w,
                     f1.x, f1.y, f1.z, f1.w,
                     f2.x, f2.y, f2.z, f2.w,
                     f3.x, f3.y, f3.z, f3.w };

    float out[L_ * H_];
    #pragma unroll
    for (int l = 0; l < L_; ++l) {
        #pragma unroll
        for (int h = 0; h < H_; ++h) {
            float acc = 0.0f;
            const float* w = &sW[(l * H_ + h) * D_];
            #pragma unroll
            for (int d = 0; d < D_; ++d)
                acc = fmaf(fr[d], w[d], acc);
            out[l * H_ + h] = acc;
        }
    }

    // 40 floats = 10 float4 stores, 16B-aligned (e*160 bytes).
    float4* dst = reinterpret_cast<float4*>(g_P + (size_t)e * (L_ * H_));
    #pragma unroll
    for (int i = 0; i < (L_ * H_) / 4; ++i) {
        float4 v = { out[4*i], out[4*i+1], out[4*i+2], out[4*i+3] };
        dst[i] = v;
    }
}

// ---------------------------------------------------------------------------
// Kernel 2: per (i, j) pair, gather P rows for the valid path edges, average,
// and scatter the 8 head values to out[h][i][j]. One thread per pair.
//
// IMPORTANT: indices arrive as int32 (the harness materializes the
// reference's int64 tensor as int32 — only float32/int32/bf16 exist in its
// dtype map). Index -1 => skip (== clip-to-0 + mask in the reference).
// Divisor = max(valid_count, 1). Any out-of-range value is treated as
// invalid (defensive: wrong-answer beats illegal-access for diagnosis).
// ---------------------------------------------------------------------------
__global__ void __launch_bounds__(256)
gather_kernel(const int* __restrict__ spe,   // [N, N, L] int32
              float* __restrict__ out)       // [H, N, N]
{
    int p = blockIdx.x * blockDim.x + threadIdx.x; // pair = i*N + j
    if (p >= N_ * N_) return;

    const int* sp = spe + (size_t)p * L_;

    float acc0 = 0.f, acc1 = 0.f, acc2 = 0.f, acc3 = 0.f;
    float acc4 = 0.f, acc5 = 0.f, acc6 = 0.f, acc7 = 0.f;
    int cnt = 0;

    #pragma unroll
    for (int l = 0; l < L_; ++l) {
        int e = __ldg(&sp[l]);
        if ((unsigned)e < (unsigned)E_) {   // e in [0, E): valid
            ++cnt;
            // P row chunk: byte offset e*160 + l*32, 16B-aligned.
            const float4* src =
                reinterpret_cast<const float4*>(g_P + (size_t)e * (L_ * H_) + l * H_);
            float4 a = src[0];
            float4 b = src[1];
            acc0 += a.x; acc1 += a.y; acc2 += a.z; acc3 += a.w;
            acc4 += b.x; acc5 += b.y; acc6 += b.z; acc7 += b.w;
        }
    }

    float inv = 1.0f / (float)(cnt > 0 ? cnt : 1);

    const int NN = N_ * N_;
    out[0 * NN + p] = acc0 * inv;
    out[1 * NN + p] = acc1 * inv;
    out[2 * NN + p] = acc2 * inv;
    out[3 * NN + p] = acc3 * inv;
    out[4 * NN + p] = acc4 * inv;
    out[5 * NN + p] = acc5 * inv;
    out[6 * NN + p] = acc6 * inv;
    out[7 * NN + p] = acc7 * inv;
}

// ---------------------------------------------------------------------------
// Launch: inputs in metadata order:
//   d_in[0] = edge_features_s      float32 [E*D]
//   d_in[1] = edge_weights         float32 [(L+1)*H*D]
//   d_in[2] = shortest_path_edges  int32   [N*N*L]   (int64 in ref -> int32)
// d_out = float32 [H*N*N]
// ---------------------------------------------------------------------------
extern "C" void kernel_launch(void* const* d_in, const int* in_sizes, int n_in,
                              void* d_out, int out_size)
{
    const float* F   = (const float*)d_in[0];
    const float* W   = (const float*)d_in[1];
    const int*   spe = (const int*)d_in[2];
    float*       out = (float*)d_out;

    project_kernel<<<(E_ + 127) / 128, 128>>>(F, W);
    gather_kernel<<<(N_ * N_ + 255) / 256, 256>>>(spe, out);
}